// round 12
// baseline (speedup 1.0000x reference)
#include <cuda_runtime.h>
#include <math.h>

#define T_DIM 512
#define B_DIM 32
#define V_DIM 4096
#define S_DIM 64
#define L_DIM 129
#define RSTR  68               // row stride in floats (16B aligned, 272B)
#define PRESCALE 14.0f         // probs stored as p * 2^14

#define LOG2E 1.4426950408889634f
#define LN2   0.6931471805599453f

// Scratch (zero-init at load; flags/done reset in-kernel each run).
__device__ float g_pc[(size_t)B_DIM * T_DIM * RSTR];  // [0]=blank, [2+j]=label j
__device__ float g_nll[B_DIM];
__device__ int   g_flag[B_DIM * T_DIM];
__device__ int   g_done;

__device__ __forceinline__ float ex2(float x) {
    float y; asm("ex2.approx.f32 %0, %1;" : "=f"(y) : "f"(x)); return y;
}
__device__ __forceinline__ float lg2(float x) {
    float y; asm("lg2.approx.f32 %0, %1;" : "=f"(y) : "f"(x)); return y;
}
__device__ __forceinline__ unsigned warp_max_u32(unsigned v) {
    unsigned r;
    asm("redux.sync.max.u32 %0, %1, 0xffffffff;" : "=r"(r) : "r"(v));
    return r;
}
__device__ __forceinline__ void st_release(int* p, int v) {
    asm volatile("st.release.gpu.global.b32 [%0], %1;" :: "l"(p), "r"(v) : "memory");
}
__device__ __forceinline__ int ld_acquire(const int* p) {
    int v;
    asm volatile("ld.acquire.gpu.global.b32 %0, [%1];" : "=r"(v) : "l"(p) : "memory");
    return v;
}
__device__ __forceinline__ void cp16cg(unsigned dst_s, const void* src) {
    asm volatile("cp.async.cg.shared.global [%0], [%1], 16;"
                 :: "r"(dst_s), "l"(src));
}

// ---------------------------------------------------------------------------
// Fused kernel. Blocks 0..31: one-warp alpha consumers chasing producers via
// per-row flags + cp.async smem ring. Blocks 32..: per-(t,b) softmax rows.
// ---------------------------------------------------------------------------
__global__ __launch_bounds__(256, 7) void k_fused(
    const float* __restrict__ acts, const int* __restrict__ labels,
    const int* __restrict__ input_len, const int* __restrict__ target_len,
    float* __restrict__ out) {
    const int tid = threadIdx.x;
    __shared__ float ring[32][RSTR];                 // 4 slots x 8 rows, 8.7KB
    __shared__ float s_s[8];
    __shared__ float s_bcast;

    if (blockIdx.x >= B_DIM) {
        // ===================== producer: softmax row (t,b) =====================
        const int row = blockIdx.x - B_DIM;          // t*B + b
        const int t   = row / B_DIM;
        const int b   = row - t * B_DIM;

        if (t >= __ldg(&input_len[b])) {             // dead row: flag & exit
            if (tid == 0) st_release(&g_flag[b * T_DIM + t], 1);
            return;
        }

        const float* __restrict__ x = acts + (size_t)row * V_DIM;
        const float4* __restrict__ x4 = reinterpret_cast<const float4*>(x);
        float s = 0.0f;
        #pragma unroll
        for (int k = 0; k < 4; ++k) {
            float4 r = __ldcs(&x4[tid + 256 * k]);
            s += ex2(r.x * LOG2E) + ex2(r.y * LOG2E)
               + ex2(r.z * LOG2E) + ex2(r.w * LOG2E);
        }
        #pragma unroll
        for (int o = 16; o; o >>= 1) s += __shfl_xor_sync(0xffffffffu, s, o);
        if ((tid & 31) == 0) s_s[tid >> 5] = s;
        __syncthreads();
        if (tid < 32) {
            float v = (tid < 8) ? s_s[tid] : 0.0f;
            #pragma unroll
            for (int o = 4; o; o >>= 1) v += __shfl_xor_sync(0xffffffffu, v, o);
            if (tid == 0) s_bcast = lg2(v);
        }
        __syncthreads();
        const float log2sum = s_bcast;

        float* __restrict__ dst = g_pc + ((size_t)b * T_DIM + t) * RSTR;
        if (tid < 64) {
            const int cls = __ldg(&labels[b * S_DIM + tid]);
            dst[2 + tid] = ex2(x[cls] * LOG2E - log2sum + PRESCALE);
        }
        if (tid == 64) dst[0] = ex2(x[0] * LOG2E - log2sum + PRESCALE);
        __syncthreads();
        if (tid == 0) st_release(&g_flag[b * T_DIM + t], 1);
        return;
    }

    // ===================== consumer: alpha for batch b =====================
    if (tid >= 32) return;                           // ONE warp only
    const int b    = blockIdx.x;
    const int lane = tid;
    const int* __restrict__ flg = g_flag + b * T_DIM;
    const float* __restrict__ base = g_pc + (size_t)b * T_DIM * RSTR;
    const int len = __ldg(&input_len[b]);

    const int* lab = labels + b * S_DIM;
    const float m0   = (lane == 0) ? 0.0f : 1.0f;
    const float sk1f = ((lane >= 1) &&
        (__ldg(&lab[2 * lane]) != __ldg(&lab[2 * lane - 1]))) ? 1.0f : 0.0f;
    const float sk3f =
        (__ldg(&lab[2 * lane + 1]) != __ldg(&lab[2 * lane])) ? 1.0f : 0.0f;

    // Wait row 0, init.
    while (__any_sync(0xffffffffu, ld_acquire(&flg[0]) == 0)) __nanosleep(128);
    __syncwarp();
    float a0 = (lane == 0) ? base[0] : 0.0f;
    float a1 = (lane == 0) ? base[2] : 0.0f;
    float a2 = 0.0f, a3 = 0.0f, a4 = 0.0f;
    float p3 = 0.0f;
    float s01 = a0 + a1;
    float s23 = 0.0f;
    int   E  = 0;

    auto step = [&](float pb, float px, float py) {
        const float n3 = fmaf(a1, sk3f, s23) * py;
        const float t3 = __shfl_up_sync(0xffffffffu, n3, 1);
        const float n0 = fmaf(p3, m0, a0) * pb;
        const float n1 = fmaf(p3, sk1f, s01) * px;
        const float n2 = (a2 + a1) * pb;
        a4 = (a4 + a3) * pb;
        s01 = n0 + n1;
        s23 = n2 + n3;
        a0 = n0; a1 = n1; a2 = n2; a3 = n3;
        p3 = t3;
    };
    auto wait8 = [&](int t0) {                       // 8 lanes poll 8 rows
        const int* f = flg + t0 + (lane & 7);
        while (__any_sync(0xffffffffu, ld_acquire(f) == 0)) __nanosleep(128);
        __syncwarp();
    };
    auto fetch8 = [&](int slot, int t0) {            // cp.async 8 rows -> slot
        const float* src = base + (size_t)t0 * RSTR;
        unsigned dst = (unsigned)__cvta_generic_to_shared(&ring[slot * 8][0]);
        #pragma unroll
        for (int c = lane; c < 136; c += 32) {       // 17 chunks x 8 rows
            const int r   = c / 17;
            const int off = c - r * 17;
            cp16cg(dst + (unsigned)(r * RSTR + off * 4) * 4u,
                   src + r * RSTR + off * 4);
        }
    };
    auto rowptr = [&](int t) -> const float* {       // t >= 1
        const int idx = t - 1;
        return &ring[((idx >> 3) & 3) * 8 + (idx & 7)][0];
    };

    const int ngr = (len - 1) >> 3;                  // groups of 8 steps
    int t = 1;
    unsigned pend = 0x3f800000u;                     // bits(1.0f)

    // Prefill 3 slots (always 3 commits to keep group accounting fixed).
    for (int k = 0; k < 3; ++k) {
        if (k < ngr) { wait8(1 + 8 * k); fetch8(k, 1 + 8 * k); }
        asm volatile("cp.async.commit_group;");
    }
    asm volatile("cp.async.wait_group 2;");
    __syncwarp();

    float pb0, px0, py0, pb1, px1, py1;
    if (ngr > 0) {
        const float* r1 = rowptr(1); const float* r2 = rowptr(2);
        pb0 = r1[0]; px0 = r1[2 + 2 * lane]; py0 = r1[3 + 2 * lane];
        pb1 = r2[0]; px1 = r2[2 + 2 * lane]; py1 = r2[3 + 2 * lane];
    }
    #pragma unroll 1
    for (int g = 0; g < ngr; ++g) {
        if (g + 3 < ngr) { wait8(1 + 8 * (g + 3)); fetch8((g + 3) & 3, 1 + 8 * (g + 3)); }
        asm volatile("cp.async.commit_group;");
        asm volatile("cp.async.wait_group 2;");      // slots g and g+1 ready
        __syncwarp();

        // Apply pending renorm to the next consumed step's prob regs.
        const int e = (int)(pend >> 23);
        E += e - 127;
        const float sc = __uint_as_float((unsigned)(254 - e) << 23);
        pb0 *= sc; px0 *= sc; py0 *= sc;

        #pragma unroll
        for (int u = 0; u < 4; ++u) {                // 4 units x 2 steps
            const float* ra = rowptr(t + 2);
            const float* rb = rowptr(t + 3);
            const float npb0 = ra[0], npx0 = ra[2 + 2 * lane], npy0 = ra[3 + 2 * lane];
            const float npb1 = rb[0], npx1 = rb[2 + 2 * lane], npy1 = rb[3 + 2 * lane];
            step(pb0, px0, py0);
            step(pb1, px1, py1);
            pb0 = npb0; px0 = npx0; py0 = npy0;
            pb1 = npb1; px1 = npx1; py1 = npy1;
            t += 2;
        }
        float m = fmaxf(fmaxf(a0, a1), fmaxf(fmaxf(a2, a3), a4));
        pend = warp_max_u32(__float_as_uint(m));
    }
    #pragma unroll 1
    for (; t < len; ++t) {                           // <=7 tail steps (LDG)
        while (__any_sync(0xffffffffu, ld_acquire(&flg[t]) == 0)) __nanosleep(128);
        __syncwarp();
        const float* r = base + (size_t)t * RSTR;
        step(r[0], r[2 + 2 * lane], r[3 + 2 * lane]);
    }

    // Finalize NLL (stash alphas in ring smem, now free).
    float* sA = &ring[0][0];
    __syncwarp();
    sA[4 * lane + 0] = a0;
    sA[4 * lane + 1] = a1;
    sA[4 * lane + 2] = a2;
    sA[4 * lane + 3] = a3;
    if (lane == 31) sA[128] = a4;
    __syncwarp();
    if (lane == 0) {
        int hi = 2 * __ldg(&target_len[b]);
        if (hi > L_DIM - 1) hi = L_DIM - 1;
        int lo = hi - 1; if (lo < 0) lo = 0;
        const float sum = sA[hi] + sA[lo];
        float v = -(lg2(sum) + (float)E - PRESCALE * (float)len) * LN2;
        if (!isfinite(v) || v > 1e29f || sum <= 0.0f) v = 0.0f;
        g_nll[b] = v;
    }

    // Wait for ALL rows of this batch flagged (dead rows flag too), reset.
    for (int i = lane; i < T_DIM; i += 32)
        while (ld_acquire(&flg[i]) == 0) __nanosleep(256);
    __syncwarp();
    for (int i = lane; i < T_DIM; i += 32) g_flag[b * T_DIM + i] = 0;

    if (lane == 0) {
        __threadfence();
        const int old = atomicAdd(&g_done, 1);
        if (old == B_DIM - 1) {                      // last consumer: reduce
            __threadfence();
            float s = 0.0f;
            #pragma unroll
            for (int i = 0; i < B_DIM; ++i)
                s += ((volatile float*)g_nll)[i];
            out[0] = s;
            g_done = 0;                              // reset for next replay
        }
    }
}

extern "C" void kernel_launch(void* const* d_in, const int* in_sizes, int n_in,
                              void* d_out, int out_size) {
    const float* acts   = (const float*)d_in[0];
    const int*   labels = (const int*)d_in[1];
    const int*   ilen   = (const int*)d_in[2];
    const int*   tlen   = (const int*)d_in[3];
    (void)in_sizes; (void)n_in; (void)out_size;

    k_fused<<<B_DIM + T_DIM * B_DIM, 256>>>(acts, labels, ilen, tlen,
                                            (float*)d_out);
}

// round 14
// speedup vs baseline: 1.0921x; 1.0921x over previous
#include <cuda_runtime.h>
#include <math.h>

#define T_DIM 512
#define B_DIM 32
#define V_DIM 4096
#define S_DIM 64
#define L_DIM 129
#define TPAD  (T_DIM + 16)      // row padding for lookahead loads
#define PRESCALE 14.0f          // probs stored as p * 2^14

#define LOG2E 1.4426950408889634f
#define LN2   0.6931471805599453f

// Scratch (zero-init at load; g_done reset in-kernel each run).
// g_pl[b][t][lane] = {blank, p(label 2*lane), p(label 2*lane+1), 0}
__device__ float4 g_pl[(size_t)B_DIM * TPAD * 32];
__device__ float  g_nll[B_DIM];
__device__ int    g_done;

__device__ __forceinline__ float ex2(float x) {
    float y; asm("ex2.approx.f32 %0, %1;" : "=f"(y) : "f"(x)); return y;
}
__device__ __forceinline__ float lg2(float x) {
    float y; asm("lg2.approx.f32 %0, %1;" : "=f"(y) : "f"(x)); return y;
}
__device__ __forceinline__ unsigned warp_max_u32(unsigned v) {
    unsigned r;
    asm("redux.sync.max.u32 %0, %1, 0xffffffff;" : "=r"(r) : "r"(v));
    return r;
}

// ---------------------------------------------------------------------------
// Kernel 1: per (t,b) row: one-pass sum(exp), gather 65 prescaled probs into
// the per-lane float4 layout. Dead rows (t >= len) skipped (~25% DRAM).
// ---------------------------------------------------------------------------
__global__ __launch_bounds__(256) void k_lse_gather(
    const float* __restrict__ acts, const int* __restrict__ labels,
    const int* __restrict__ input_len) {
    const int row = blockIdx.x;            // t*B + b
    const int t   = row / B_DIM;
    const int b   = row - t * B_DIM;
    if (t >= __ldg(&input_len[b])) return; // dead row

    const float* __restrict__ x = acts + (size_t)row * V_DIM;
    const int tid = threadIdx.x;

    const float4* __restrict__ x4 = reinterpret_cast<const float4*>(x);
    float s = 0.0f;
    #pragma unroll
    for (int k = 0; k < 4; ++k) {
        float4 r = __ldcs(&x4[tid + 256 * k]);   // stream, evict-first
        s += ex2(r.x * LOG2E) + ex2(r.y * LOG2E)
           + ex2(r.z * LOG2E) + ex2(r.w * LOG2E);
    }

    __shared__ float s_s[8];
    __shared__ float s_bcast;
    #pragma unroll
    for (int o = 16; o; o >>= 1) s += __shfl_xor_sync(0xffffffffu, s, o);
    if ((tid & 31) == 0) s_s[tid >> 5] = s;
    __syncthreads();
    if (tid < 32) {
        float v = (tid < 8) ? s_s[tid] : 0.0f;
        #pragma unroll
        for (int o = 4; o; o >>= 1) v += __shfl_xor_sync(0xffffffffu, v, o);
        if (tid == 0) s_bcast = lg2(v);
    }
    __syncthreads();
    const float log2sum = s_bcast;

    if (tid < 32) {
        const int c0 = __ldg(&labels[b * S_DIM + 2 * tid]);
        const int c1 = __ldg(&labels[b * S_DIM + 2 * tid + 1]);
        float4 v;
        v.x = ex2(x[0]  * LOG2E - log2sum + PRESCALE);   // broadcast load
        v.y = ex2(x[c0] * LOG2E - log2sum + PRESCALE);
        v.z = ex2(x[c1] * LOG2E - log2sum + PRESCALE);
        v.w = 0.0f;
        g_pl[((size_t)b * TPAD + t) * 32 + tid] = v;
    }
}

// ---------------------------------------------------------------------------
// Kernel 2: scaled linear-domain CTC alpha. ONE warp per batch, no smem
// preload: probs streamed from L2 via per-lane LDG.128 into a 16-row
// register double-buffer (A/B). Renorm period 8 with LAG-0 apply (issue at
// group end, apply at next group start — R11-validated window; a longer lag
// overflows f32). Last block reduces the 32 NLLs.
// ---------------------------------------------------------------------------
__global__ __launch_bounds__(32) void k_alpha(
    const int* __restrict__ labels,
    const int* __restrict__ input_len,
    const int* __restrict__ target_len,
    float* __restrict__ out) {
    __shared__ float sA[132];
    const int b    = blockIdx.x;
    const int lane = threadIdx.x;
    const int len  = __ldg(&input_len[b]);

    const float4* __restrict__ pl = g_pl + (size_t)b * TPAD * 32 + lane;
    // row t lives at pl[t*32]

    const int* lab = labels + b * S_DIM;
    const float m0   = (lane == 0) ? 0.0f : 1.0f;
    const float sk1f = ((lane >= 1) &&
        (__ldg(&lab[2 * lane]) != __ldg(&lab[2 * lane - 1]))) ? 1.0f : 0.0f;
    const float sk3f =
        (__ldg(&lab[2 * lane + 1]) != __ldg(&lab[2 * lane])) ? 1.0f : 0.0f;

    const float4 r0 = __ldg(&pl[0]);
    float a0 = (lane == 0) ? r0.x : 0.0f;
    float a1 = (lane == 0) ? r0.y : 0.0f;
    float a2 = 0.0f, a3 = 0.0f, a4 = 0.0f;
    float p3 = 0.0f;
    float s01 = a0 + a1;
    float s23 = 0.0f;
    int   E  = 0;

    auto step = [&](float4 pr) {
        const float n3 = fmaf(a1, sk3f, s23) * pr.z;
        const float t3 = __shfl_up_sync(0xffffffffu, n3, 1);
        const float n0 = fmaf(p3, m0, a0) * pr.x;
        const float n1 = fmaf(p3, sk1f, s01) * pr.y;
        const float n2 = (a2 + a1) * pr.x;
        a4 = (a4 + a3) * pr.x;        // real only on lane31; junk benign
        s01 = n0 + n1;
        s23 = n2 + n3;
        a0 = n0; a1 = n1; a2 = n2; a3 = n3;
        p3 = t3;                      // lane0 junk masked by m0/sk1f
    };
    auto apply = [&](unsigned pend, float4& pr) {
        const int e = (int)(pend >> 23);
        E += e - 127;
        const float sc = __uint_as_float((unsigned)(254 - e) << 23);
        pr.x *= sc; pr.y *= sc; pr.z *= sc;
    };
    auto issue = [&]() -> unsigned {
        const float m = fmaxf(fmaxf(a0, a1), fmaxf(fmaxf(a2, a3), a4));
        return warp_max_u32(__float_as_uint(m));
    };

    // Register double-buffer: A = rows t..t+7, B = rows t+8..t+15.
    float4 A[8], B[8];
    #pragma unroll
    for (int i = 0; i < 8; ++i) A[i] = __ldg(&pl[(1 + i) * 32]);
    #pragma unroll
    for (int i = 0; i < 8; ++i) B[i] = __ldg(&pl[(9 + i) * 32]);

    int t = 1;
    unsigned pend = 0x3f800000u;                 // bits(1.0f): identity

    #pragma unroll 1
    while (t <= len - 16) {
        apply(pend, A[0]);
        #pragma unroll
        for (int i = 0; i < 8; ++i) {
            const float4 n = __ldg(&pl[(t + 16 + i) * 32]);
            step(A[i]);
            A[i] = n;
        }
        pend = issue();

        apply(pend, B[0]);
        #pragma unroll
        for (int i = 0; i < 8; ++i) {
            const float4 n = __ldg(&pl[(t + 24 + i) * 32]);
            step(B[i]);
            B[i] = n;
        }
        pend = issue();
        t += 16;
    }

    // Tail: 0..15 steps; rows resident in A (t..t+7) / B (t+8..t+15).
    // Renorm windows stay <= 8 steps.
    const int r = len - t;
    if (r > 0) {
        apply(pend, A[0]);
        #pragma unroll
        for (int i = 0; i < 8; ++i)
            if (i < r) step(A[i]);
        if (r > 8) {
            pend = issue();
            apply(pend, B[0]);
            #pragma unroll
            for (int i = 0; i < 7; ++i)
                if (8 + i < r) step(B[i]);
        }
    }

    // Stash alphas and finalize.
    __syncwarp();
    sA[4 * lane + 0] = a0;
    sA[4 * lane + 1] = a1;
    sA[4 * lane + 2] = a2;
    sA[4 * lane + 3] = a3;
    if (lane == 31) sA[128] = a4;
    __syncwarp();

    if (lane == 0) {
        int hi = 2 * __ldg(&target_len[b]);
        if (hi > L_DIM - 1) hi = L_DIM - 1;
        int lo = hi - 1; if (lo < 0) lo = 0;
        const float sum = sA[hi] + sA[lo];
        float v = -(lg2(sum) + (float)E - PRESCALE * (float)len) * LN2;
        if (!isfinite(v) || v > 1e29f || sum <= 0.0f) v = 0.0f;
        g_nll[b] = v;

        __threadfence();
        const int old = atomicAdd(&g_done, 1);
        if (old == B_DIM - 1) {                  // last block: reduce
            __threadfence();
            float s = 0.0f;
            #pragma unroll
            for (int i = 0; i < B_DIM; ++i)
                s += ((volatile float*)g_nll)[i];
            out[0] = s;
            g_done = 0;                          // reset for next replay
        }
    }
}

extern "C" void kernel_launch(void* const* d_in, const int* in_sizes, int n_in,
                              void* d_out, int out_size) {
    const float* acts   = (const float*)d_in[0];
    const int*   labels = (const int*)d_in[1];
    const int*   ilen   = (const int*)d_in[2];
    const int*   tlen   = (const int*)d_in[3];
    (void)in_sizes; (void)n_in; (void)out_size;

    k_lse_gather<<<T_DIM * B_DIM, 256>>>(acts, labels, ilen);
    k_alpha<<<B_DIM, 32>>>(labels, ilen, tlen, (float*)d_out);
}